// round 7
// baseline (speedup 1.0000x reference)
#include <cuda_runtime.h>
#include <math.h>

#define BB 256
#define NN 384
#define DD 128
#define NEGV -1e9f
#define NTHR 384
#define NWARP 12
#define USTRIDE 136   // 16B-aligned row stride for U table

// SMEM float offsets
#define OFF_U     0
#define OFF_QHB   (NN * USTRIDE)           // 52224
#define OFF_QV1F  (OFF_QHB + DD)           // 52352
#define OFF_RV    (OFF_QV1F + DD)          // 52480  (32: parity x 16)
#define OFF_RI    (OFF_RV + 32)            // 52512
#define OFF_RS    (OFF_RI + 32)            // 52544
#define OFF_SCR   (OFF_RS + 32)            // 52576 -> byte 210304, 16B aligned
#define SMEM_FLOATS (OFF_SCR + 32 * DD)    // 56672 floats = 226688 B

// ---------------------------------------------------------------------------
// packed fp32x2 helpers (sm_103a FFMA2 path)
// ---------------------------------------------------------------------------
__device__ __forceinline__ void ffma2(unsigned long long& d,
                                      unsigned long long a,
                                      unsigned long long b) {
    asm("fma.rn.f32x2 %0, %1, %2, %0;" : "+l"(d) : "l"(a), "l"(b));
}
__device__ __forceinline__ unsigned long long pack2(float lo, float hi) {
    unsigned long long r;
    asm("mov.b64 %0, {%1, %2};" : "=l"(r) : "f"(lo), "f"(hi));
    return r;
}
__device__ __forceinline__ float2 unpack2(unsigned long long v) {
    float2 f;
    asm("mov.b64 {%0, %1}, %2;" : "=f"(f.x), "=f"(f.y) : "l"(v));
    return f;
}

// ---------------------------------------------------------------------------
// Bit-faithful port of XLA's EmitFastTanh (with_fma=true). DO NOT TOUCH:
// the route's tie structure depends on this exact function.
// ---------------------------------------------------------------------------
__device__ __forceinline__ float xla_tanh(float x) {
    const float kClamp = 7.99881172180175781f;
    float xc = fminf(fmaxf(x, -kClamp), kClamp);
    float x2 = xc * xc;
    float p = fmaf(x2, -2.76076847742355e-16f, 2.00018790482477e-13f);
    p = fmaf(x2, p, -8.60467152213735e-11f);
    p = fmaf(x2, p,  5.12229709037114e-08f);
    p = fmaf(x2, p,  1.48572235717979e-05f);
    p = fmaf(x2, p,  6.37261928875436e-04f);
    p = fmaf(x2, p,  4.89352455891786e-03f);
    p = xc * p;
    float q = fmaf(x2, 1.19825839466702e-06f, 1.18534705686654e-04f);
    q = fmaf(x2, q, 2.26843463243900e-03f);
    q = fmaf(x2, q, 4.89352518554385e-03f);
    float r = p / q;
    return (fabsf(x) < 0.0004f) ? x : r;
}

extern __shared__ float smem[];

__global__ void __launch_bounds__(NTHR, 1)
decode_kernel(const float* __restrict__ hvec,
              const float* __restrict__ hbar,
              const float* __restrict__ qvp,
              const float* __restrict__ kvp,
              const float* __restrict__ vec1,
              const float* __restrict__ vecf,
              float* __restrict__ out)
{
    const int b    = blockIdx.x;
    const int tid  = threadIdx.x;
    const int lane = tid & 31;
    const int wid  = tid >> 5;

    float* Us   = smem + OFF_U;
    float* qhb  = smem + OFF_QHB;
    float* qv1f = smem + OFF_QV1F;
    float* rv   = smem + OFF_RV;
    int*   ri   = (int*)(smem + OFF_RI);
    float* rs   = smem + OFF_RS;
    float* scr  = smem + OFF_SCR;

    const float* hrow = hvec + ((size_t)b * NN + tid) * DD;

    // ================= PROLOGUE =================
    // Phase A: stage qvp flat into U area; hbar row & (vec1+vecf) into scratch
    for (int i = tid; i < DD * DD; i += NTHR) Us[i] = qvp[i];
    if (tid < DD) {
        scr[tid]      = hbar[b * DD + tid];
        scr[DD + tid] = vec1[tid] + vecf[tid];
    }
    __syncthreads();

    // Phase B: U[n][ij] = sum_k qvp[k][ij] * h[n][k] (f32x2 lanes, seq-k each)
    // Row = 128 floats = 32 ulonglong2; Ur2 has 64 packed lanes (all written).
    unsigned long long Ur2[64];
    #pragma unroll
    for (int j = 0; j < 64; j++) Ur2[j] = 0ull;
    for (int kc = 0; kc < DD; kc += 16) {
        float4 h4[4];
        #pragma unroll
        for (int i = 0; i < 4; i++) h4[i] = ((const float4*)hrow)[kc / 4 + i];
        const float* hs = (const float*)h4;
        #pragma unroll
        for (int i = 0; i < 16; i++) {
            unsigned long long hk2 = pack2(hs[i], hs[i]);
            const ulonglong2* row = (const ulonglong2*)(Us + (kc + i) * DD);
            #pragma unroll
            for (int j = 0; j < 32; j++) {       // FULL row: 32 ulonglong2
                ulonglong2 w = row[j];
                ffma2(Ur2[2 * j + 0], w.x, hk2);
                ffma2(Ur2[2 * j + 1], w.y, hk2);
            }
        }
    }
    // Phase B2: qhb = Wq^T hbar ; qv1f = Wq^T (vec1+vecf)   (threads 0..127)
    if (tid < DD) {
        float a0 = 0.f, a1 = 0.f, a2 = 0.f, a3 = 0.f;
        float c0 = 0.f, c1 = 0.f, c2 = 0.f, c3 = 0.f;
        #pragma unroll 8
        for (int k = 0; k < DD; k += 4) {
            float w0 = Us[(k + 0) * DD + tid];
            float w1 = Us[(k + 1) * DD + tid];
            float w2 = Us[(k + 2) * DD + tid];
            float w3 = Us[(k + 3) * DD + tid];
            a0 = fmaf(w0, scr[k + 0], a0); c0 = fmaf(w0, scr[DD + k + 0], c0);
            a1 = fmaf(w1, scr[k + 1], a1); c1 = fmaf(w1, scr[DD + k + 1], c1);
            a2 = fmaf(w2, scr[k + 2], a2); c2 = fmaf(w2, scr[DD + k + 2], c2);
            a3 = fmaf(w3, scr[k + 3], a3); c3 = fmaf(w3, scr[DD + k + 3], c3);
        }
        qhb[tid]  = (a0 + a1) + (a2 + a3);
        qv1f[tid] = (c0 + c1) + (c2 + c3);
    }
    __syncthreads();

    // Phase C: write FULL U row (32 ulonglong2) -> strided SMEM
    {
        ulonglong2* myrow = (ulonglong2*)(Us + tid * USTRIDE);
        #pragma unroll
        for (int j = 0; j < 32; j++) {
            ulonglong2 w; w.x = Ur2[2 * j]; w.y = Ur2[2 * j + 1];
            myrow[j] = w;
        }
    }

    // Phase D: KV (f32x2 lanes, sequential-k per lane), 4 staged chunks
    unsigned long long KV2[64];
    #pragma unroll
    for (int j = 0; j < 64; j++) KV2[j] = 0ull;
    for (int c = 0; c < 4; c++) {
        __syncthreads();
        for (int i = tid; i < 32 * DD; i += NTHR) scr[i] = kvp[c * 32 * DD + i];
        __syncthreads();
        for (int kc = 0; kc < 32; kc += 16) {
            float4 h4[4];
            #pragma unroll
            for (int i = 0; i < 4; i++)
                h4[i] = ((const float4*)hrow)[(c * 32 + kc) / 4 + i];
            const float* hs = (const float*)h4;
            #pragma unroll
            for (int i = 0; i < 16; i++) {
                unsigned long long hk2 = pack2(hs[i], hs[i]);
                const ulonglong2* row = (const ulonglong2*)(scr + (kc + i) * DD);
                #pragma unroll
                for (int j = 0; j < 32; j++) {   // FULL row
                    ulonglong2 w = row[j];
                    ffma2(KV2[2 * j + 0], w.x, hk2);
                    ffma2(KV2[2 * j + 1], w.y, hk2);
                }
            }
        }
    }
    __syncthreads();

    // Phase E: sHB = qhb.KV ; sV = qv1f.KV  (scalar, one-time)
    float sHB, sV;
    {
        float a0 = 0.f, a1 = 0.f, c0 = 0.f, c1 = 0.f;
        #pragma unroll
        for (int j = 0; j < 64; j++) {
            float2 kvf = unpack2(KV2[j]);
            float q0 = qhb[2 * j], q1 = qhb[2 * j + 1];
            float v0 = qv1f[2 * j], v1 = qv1f[2 * j + 1];
            a0 = fmaf(q0, kvf.x, a0); a1 = fmaf(q1, kvf.y, a1);
            c0 = fmaf(v0, kvf.x, c0); c1 = fmaf(v1, kvf.y, c1);
        }
        sHB = a0 + a1;
        sV  = c0 + c1;
    }

    // ================= MAIN DECODE LOOP (1 barrier/step) =================
    bool  vis  = false;
    float logp = 0.f;
    float sbf  = 0.f;
    int   a    = -1;

    for (int t = 0; t < NN; t++) {
        float s;
        if (t == 0) {
            s = sHB + sV;
        } else {
            // dt = U[a] . KV over ALL 128 dims (32 ulonglong2)
            const ulonglong2* ur = (const ulonglong2*)(Us + a * USTRIDE);
            unsigned long long d0 = 0ull, d1 = 0ull, d2 = 0ull, d3 = 0ull;
            #pragma unroll
            for (int i = 0; i < 32; i += 2) {
                ulonglong2 u0 = ur[i];
                ulonglong2 u1 = ur[i + 1];
                ffma2(d0, u0.x, KV2[2 * i + 0]);
                ffma2(d1, u0.y, KV2[2 * i + 1]);
                ffma2(d2, u1.x, KV2[2 * i + 2]);
                ffma2(d3, u1.y, KV2[2 * i + 3]);
            }
            float2 f0 = unpack2(d0), f1 = unpack2(d1);
            float2 f2 = unpack2(d2), f3 = unpack2(d3);
            float dt = ((f0.x + f0.y) + (f1.x + f1.y)) +
                       ((f2.x + f2.y) + (f3.x + f3.y));
            if (t == 1) sbf = sHB + dt;   // first := chosen at t=0
            s = sbf + dt;
        }

        float score  = 10.f * xla_tanh(s * 0.25f);
        float masked = vis ? NEGV : score;
        float ep     = __expf(masked);     // exp(-1e9) -> 0

        // fused warp argmax (lowest index on ties) + exp-sum
        float v = masked; int idx = tid; float es = ep;
        #pragma unroll
        for (int o = 16; o > 0; o >>= 1) {
            float v2 = __shfl_xor_sync(0xffffffffu, v, o);
            int   i2 = __shfl_xor_sync(0xffffffffu, idx, o);
            float e2 = __shfl_xor_sync(0xffffffffu, es, o);
            es += e2;
            if (v2 > v || (v2 == v && i2 < idx)) { v = v2; idx = i2; }
        }
        const int par = (t & 1) ? 16 : 0;   // parity double-buffer
        if (lane == 0) { rv[par + wid] = v; ri[par + wid] = idx; rs[par + wid] = es; }
        __syncthreads();  // single barrier per step

        // redundant final combine by ALL threads (broadcast LDS)
        float m  = rv[par];
        int   am = ri[par];
        float ss = rs[par];
        #pragma unroll
        for (int w = 1; w < NWARP; w++) {
            float v2 = rv[par + w];
            int   i2 = ri[par + w];
            ss += rs[par + w];
            if (v2 > m || (v2 == m && i2 < am)) { m = v2; am = i2; }
        }
        a = am;
        if (tid == a) vis = true;
        if (tid == 0) {
            out[t * BB + b] = (float)a;
            logp += m - __logf(ss);  // = -log(sum exp(masked - max))
        }
    }

    if (tid == 0) out[NN * BB + b] = logp;
}

// ---------------------------------------------------------------------------
extern "C" void kernel_launch(void* const* d_in, const int* in_sizes, int n_in,
                              void* d_out, int out_size) {
    const float* hvec = (const float*)d_in[0];
    const float* hbar = (const float*)d_in[1];
    const float* qvp  = (const float*)d_in[2];
    const float* kvp  = (const float*)d_in[3];
    const float* vec1 = (const float*)d_in[4];
    const float* vecf = (const float*)d_in[5];
    float* out = (float*)d_out;

    size_t smem_bytes = (size_t)SMEM_FLOATS * sizeof(float);  // 226688 B
    cudaFuncSetAttribute(decode_kernel,
                         cudaFuncAttributeMaxDynamicSharedMemorySize,
                         (int)smem_bytes);
    decode_kernel<<<BB, NTHR, smem_bytes>>>(hvec, hbar, qvp, kvp, vec1, vecf, out);
}

// round 8
// speedup vs baseline: 1.4305x; 1.4305x over previous
#include <cuda_runtime.h>
#include <math.h>

#define BB 256
#define NN 384
#define DD 128
#define NEGV -1e9f
#define NWARP 12

// ---------------- device scratch (static, no allocation) ----------------
__device__ float g_A[DD * DD];                 // A[k][m] = qv_k . kv_m
__device__ float g_hT[BB * DD * NN];           // h^T  [b][d][n]   (50 MB)
__device__ float g_MT[BB * DD * NN];           // M^T  [b][m][a]   (50 MB)
__device__ float g_G[(size_t)BB * NN * NN];    // G    [b][a][n]   (151 MB)
__device__ float g_hbarA[BB * DD];             // hbar^T A  per batch
__device__ float g_vA[DD];                     // (vec1+vecf)^T A

// ---------------- packed fp32x2 helpers ----------------
__device__ __forceinline__ void ffma2(unsigned long long& d,
                                      unsigned long long a,
                                      unsigned long long b) {
    asm("fma.rn.f32x2 %0, %1, %2, %0;" : "+l"(d) : "l"(a), "l"(b));
}
__device__ __forceinline__ unsigned long long pack2(float lo, float hi) {
    unsigned long long r;
    asm("mov.b64 %0, {%1, %2};" : "=l"(r) : "f"(lo), "f"(hi));
    return r;
}

// ---------------------------------------------------------------------------
// Bit-faithful port of XLA's EmitFastTanh (with_fma=true). DO NOT TOUCH.
// ---------------------------------------------------------------------------
__device__ __forceinline__ float xla_tanh(float x) {
    const float kClamp = 7.99881172180175781f;
    float xc = fminf(fmaxf(x, -kClamp), kClamp);
    float x2 = xc * xc;
    float p = fmaf(x2, -2.76076847742355e-16f, 2.00018790482477e-13f);
    p = fmaf(x2, p, -8.60467152213735e-11f);
    p = fmaf(x2, p,  5.12229709037114e-08f);
    p = fmaf(x2, p,  1.48572235717979e-05f);
    p = fmaf(x2, p,  6.37261928875436e-04f);
    p = fmaf(x2, p,  4.89352455891786e-03f);
    p = xc * p;
    float q = fmaf(x2, 1.19825839466702e-06f, 1.18534705686654e-04f);
    q = fmaf(x2, q, 2.26843463243900e-03f);
    q = fmaf(x2, q, 4.89352518554385e-03f);
    float r = p / q;
    return (fabsf(x) < 0.0004f) ? x : r;
}

// ---------------------------------------------------------------------------
// K_A: A[k][m] = sum_j qv[k][j] * kv[m][j]
// ---------------------------------------------------------------------------
__global__ void kA(const float* __restrict__ qv, const float* __restrict__ kv) {
    __shared__ float wk[DD];
    int m = blockIdx.x, k = threadIdx.x;
    wk[k] = kv[m * DD + k];
    __syncthreads();
    float s = 0.f;
    #pragma unroll 8
    for (int j = 0; j < DD; j++) s = fmaf(qv[k * DD + j], wk[j], s);
    g_A[k * DD + m] = s;
}

// ---------------------------------------------------------------------------
// K_T: hT[b][d][n] = hvec[b][n][d]  (32x32 smem tiles, coalesced both sides)
// ---------------------------------------------------------------------------
__global__ void kT(const float* __restrict__ hvec) {
    __shared__ float tile[32][33];
    int b = blockIdx.z;
    int n0 = blockIdx.x * 32, d0 = blockIdx.y * 32;
    int tx = threadIdx.x, ty = threadIdx.y;   // 32 x 8
    #pragma unroll
    for (int i = 0; i < 32; i += 8)
        tile[ty + i][tx] = hvec[((size_t)b * NN + n0 + ty + i) * DD + d0 + tx];
    __syncthreads();
    #pragma unroll
    for (int i = 0; i < 32; i += 8)
        g_hT[((size_t)b * DD + d0 + ty + i) * NN + n0 + tx] = tile[tx][ty + i];
}

// ---------------------------------------------------------------------------
// K_MT: MT[b][m][a] = sum_k A[k][m] * h[a][k]   (FFMA2, seq-k per lane)
//       + g_hbarA[b][m] = sum_k hbar[b][k]*A[k][m]; g_vA (b==0 only)
// smem: As[16384] + hTs[32*384] + sbv[256]  = 115712 B
// ---------------------------------------------------------------------------
extern __shared__ float dynsm[];
__global__ void __launch_bounds__(384, 1)
kMT(const float* __restrict__ hbar,
    const float* __restrict__ vec1, const float* __restrict__ vecf) {
    float* As  = dynsm;             // [DD*DD]
    float* hTs = dynsm + DD * DD;   // [32*NN]
    float* sbv = hTs + 32 * NN;     // [256]
    int b = blockIdx.x, tid = threadIdx.x;
    int g = tid >> 7, m = tid & 127;

    for (int i = tid; i < DD * DD; i += 384) As[i] = g_A[i];
    if (tid < DD) {
        sbv[tid]      = hbar[b * DD + tid];
        sbv[DD + tid] = vec1[tid] + vecf[tid];
    }

    unsigned long long acc2[64];
    #pragma unroll
    for (int j = 0; j < 64; j++) acc2[j] = 0ull;

    const float* hTb = g_hT + (size_t)b * DD * NN;
    for (int c = 0; c < 4; c++) {
        __syncthreads();
        const float4* src = (const float4*)(hTb + c * 32 * NN);
        for (int i = tid; i < 32 * NN / 4; i += 384)
            ((float4*)hTs)[i] = src[i];
        __syncthreads();
        for (int kk = 0; kk < 32; kk++) {
            float av = As[(c * 32 + kk) * DD + m];
            unsigned long long a2 = pack2(av, av);
            const ulonglong2* hr = (const ulonglong2*)(hTs + kk * NN + g * 128);
            #pragma unroll
            for (int j = 0; j < 32; j++) {
                ulonglong2 h2 = hr[j];
                ffma2(acc2[2 * j + 0], h2.x, a2);
                ffma2(acc2[2 * j + 1], h2.y, a2);
            }
        }
    }
    // store MT[b][m][g*128 .. +128]
    ulonglong2* dst = (ulonglong2*)(g_MT + ((size_t)b * DD + m) * NN + g * 128);
    #pragma unroll
    for (int j = 0; j < 32; j++) {
        ulonglong2 w; w.x = acc2[2 * j]; w.y = acc2[2 * j + 1];
        dst[j] = w;
    }

    __syncthreads();
    if (tid < DD) {
        float acc = 0.f;
        #pragma unroll 8
        for (int k = 0; k < DD; k++) acc = fmaf(sbv[k], As[k * DD + tid], acc);
        g_hbarA[b * DD + tid] = acc;
    } else if (tid < 2 * DD && b == 0) {
        int mm = tid - DD;
        float acc = 0.f;
        #pragma unroll 8
        for (int k = 0; k < DD; k++) acc = fmaf(sbv[DD + k], As[k * DD + mm], acc);
        g_vA[mm] = acc;
    }
}

// ---------------------------------------------------------------------------
// K_G: G[b][a][n] = sum_d MT[d][a] * hT[d][n].  128x128 output tile per CTA,
// 256 threads, 8x8 register tile, FFMA2, two 64-d smem chunks (67.6 KB).
// ---------------------------------------------------------------------------
#define GSTR 132
__global__ void __launch_bounds__(256, 1) kG() {
    float* Ms = dynsm;               // [64][GSTR]
    float* Hs = dynsm + 64 * GSTR;   // [64][GSTR]
    int b = blockIdx.z, ab = blockIdx.y, nb = blockIdx.x;
    int tid = threadIdx.x;
    int ty = tid >> 4, tx = tid & 15;

    const float* MTb = g_MT + (size_t)b * DD * NN;
    const float* hTb = g_hT + (size_t)b * DD * NN;

    unsigned long long acc2[32];   // [r][c2] = acc2[r*4+c2]
    #pragma unroll
    for (int j = 0; j < 32; j++) acc2[j] = 0ull;

    for (int dc = 0; dc < 2; dc++) {
        __syncthreads();
        for (int i = tid; i < 64 * 32; i += 256) {
            int d = i >> 5, a4 = i & 31;
            ((float4*)(Ms + d * GSTR))[a4] =
                ((const float4*)(MTb + (size_t)(dc * 64 + d) * NN + ab * 128))[a4];
            ((float4*)(Hs + d * GSTR))[a4] =
                ((const float4*)(hTb + (size_t)(dc * 64 + d) * NN + nb * 128))[a4];
        }
        __syncthreads();
        #pragma unroll 4
        for (int d = 0; d < 64; d++) {
            const float4* ar = (const float4*)(Ms + d * GSTR + ty * 8);
            float4 A0 = ar[0], A1 = ar[1];
            const ulonglong2* br = (const ulonglong2*)(Hs + d * GSTR + tx * 8);
            ulonglong2 B0 = br[0], B1 = br[1];
            unsigned long long b2[4] = {B0.x, B0.y, B1.x, B1.y};
            float af[8] = {A0.x, A0.y, A0.z, A0.w, A1.x, A1.y, A1.z, A1.w};
            #pragma unroll
            for (int r = 0; r < 8; r++) {
                unsigned long long ad = pack2(af[r], af[r]);
                #pragma unroll
                for (int c = 0; c < 4; c++) ffma2(acc2[r * 4 + c], b2[c], ad);
            }
        }
    }
    #pragma unroll
    for (int r = 0; r < 8; r++) {
        ulonglong2* dst = (ulonglong2*)(g_G +
            ((size_t)b * NN + ab * 128 + ty * 8 + r) * NN + nb * 128 + tx * 8);
        ulonglong2 w0; w0.x = acc2[r * 4 + 0]; w0.y = acc2[r * 4 + 1];
        ulonglong2 w1; w1.x = acc2[r * 4 + 2]; w1.y = acc2[r * 4 + 3];
        dst[0] = w0; dst[1] = w1;
    }
}

// ---------------------------------------------------------------------------
// K_D: sequential greedy decode. One CTA per batch, tiny smem -> 1 wave.
// ---------------------------------------------------------------------------
__global__ void __launch_bounds__(384) kD(const float* __restrict__ hvec,
                                          float* __restrict__ out) {
    __shared__ float sb[DD], sv[DD];
    __shared__ float rv[32]; __shared__ int ri[32]; __shared__ float rs[32];
    const int b = blockIdx.x, tid = threadIdx.x;
    const int lane = tid & 31, wid = tid >> 5;

    if (tid < DD) { sb[tid] = g_hbarA[b * DD + tid]; sv[tid] = g_vA[tid]; }
    __syncthreads();

    // sHB_n = hbarA . h_n ; sV_n = vA . h_n   (one-time, 4-acc trees)
    float sHB, sV;
    {
        const float4* h4 = (const float4*)(hvec + ((size_t)b * NN + tid) * DD);
        float a0 = 0.f, a1 = 0.f, a2 = 0.f, a3 = 0.f;
        float c0 = 0.f, c1 = 0.f, c2 = 0.f, c3 = 0.f;
        #pragma unroll
        for (int j = 0; j < 32; j++) {
            float4 h = h4[j];
            a0 = fmaf(h.x, sb[4 * j + 0], a0); c0 = fmaf(h.x, sv[4 * j + 0], c0);
            a1 = fmaf(h.y, sb[4 * j + 1], a1); c1 = fmaf(h.y, sv[4 * j + 1], c1);
            a2 = fmaf(h.z, sb[4 * j + 2], a2); c2 = fmaf(h.z, sv[4 * j + 2], c2);
            a3 = fmaf(h.w, sb[4 * j + 3], a3); c3 = fmaf(h.w, sv[4 * j + 3], c3);
        }
        sHB = (a0 + a1) + (a2 + a3);
        sV  = (c0 + c1) + (c2 + c3);
    }

    const float* Gb = g_G + (size_t)b * NN * NN;
    bool  vis  = false;
    float logp = 0.f, sbf = 0.f;
    int   a    = 0;

    for (int t = 0; t < NN; t++) {
        float s;
        if (t == 0) {
            s = sHB + sV;
        } else {
            float gv = __ldg(Gb + (size_t)a * NN + tid);   // coalesced G row
            if (t == 1) sbf = sHB + gv;   // first == last at t=1
            s = sbf + gv;
        }

        float score  = 10.f * xla_tanh(s * 0.25f);
        float masked = vis ? NEGV : score;
        float ep     = __expf(masked);

        float v = masked; int idx = tid; float es = ep;
        #pragma unroll
        for (int o = 16; o > 0; o >>= 1) {
            float v2 = __shfl_xor_sync(0xffffffffu, v, o);
            int   i2 = __shfl_xor_sync(0xffffffffu, idx, o);
            float e2 = __shfl_xor_sync(0xffffffffu, es, o);
            es += e2;
            if (v2 > v || (v2 == v && i2 < idx)) { v = v2; idx = i2; }
        }
        const int par = (t & 1) ? 16 : 0;
        if (lane == 0) { rv[par + wid] = v; ri[par + wid] = idx; rs[par + wid] = es; }
        __syncthreads();

        float m  = rv[par];
        int   am = ri[par];
        float ss = rs[par];
        #pragma unroll
        for (int w = 1; w < NWARP; w++) {
            float v2 = rv[par + w];
            int   i2 = ri[par + w];
            ss += rs[par + w];
            if (v2 > m || (v2 == m && i2 < am)) { m = v2; am = i2; }
        }
        a = am;
        if (tid == a) vis = true;
        if (tid == 0) {
            out[t * BB + b] = (float)a;
            logp += m - __logf(ss);
        }
    }
    if (tid == 0) out[NN * BB + b] = logp;
}

// ---------------------------------------------------------------------------
extern "C" void kernel_launch(void* const* d_in, const int* in_sizes, int n_in,
                              void* d_out, int out_size) {
    const float* hvec = (const float*)d_in[0];
    const float* hbar = (const float*)d_in[1];
    const float* qvp  = (const float*)d_in[2];
    const float* kvp  = (const float*)d_in[3];
    const float* vec1 = (const float*)d_in[4];
    const float* vecf = (const float*)d_in[5];
    float* out = (float*)d_out;

    const int smMT = (DD * DD + 32 * NN + 256) * 4;   // 115712 B
    const int smG  = 2 * 64 * GSTR * 4;               //  67584 B
    cudaFuncSetAttribute(kMT, cudaFuncAttributeMaxDynamicSharedMemorySize, smMT);
    cudaFuncSetAttribute(kG,  cudaFuncAttributeMaxDynamicSharedMemorySize, smG);

    kA<<<DD, DD>>>(qvp, kvp);
    kT<<<dim3(NN / 32, DD / 32, BB), dim3(32, 8)>>>(hvec);
    kMT<<<BB, 384, smMT>>>(hbar, vec1, vecf);
    kG<<<dim3(NN / 128, NN / 128, BB), 256, smG>>>();
    kD<<<BB, 384>>>(hvec, out);
}

// round 9
// speedup vs baseline: 1.6423x; 1.1480x over previous
#include <cuda_runtime.h>
#include <math.h>

#define BB 256
#define NN 384
#define DD 128
#define NEGV -1e9f
#define NWARP 12
#define GSTR 132

// ---------------- device scratch (static, no allocation) ----------------
__device__ float g_A[DD * DD];                 // A[k][m] = qv_k . kv_m
__device__ float g_hT[BB * DD * NN];           // h^T  [b][d][n]
__device__ float g_MT[BB * DD * NN];           // M^T  [b][m][a]
__device__ float g_G[(size_t)BB * NN * NN];    // G    [b][a][n]
__device__ float g_hbarA[BB * DD];
__device__ float g_vA[DD];

// ---------------- packed fp32x2 helpers ----------------
__device__ __forceinline__ void ffma2(unsigned long long& d,
                                      unsigned long long a,
                                      unsigned long long b) {
    asm("fma.rn.f32x2 %0, %1, %2, %0;" : "+l"(d) : "l"(a), "l"(b));
}
__device__ __forceinline__ unsigned long long pack2(float lo, float hi) {
    unsigned long long r;
    asm("mov.b64 %0, {%1, %2};" : "=l"(r) : "f"(lo), "f"(hi));
    return r;
}

// ---------------------------------------------------------------------------
// Bit-faithful port of XLA's EmitFastTanh (with_fma=true). DO NOT TOUCH.
// ---------------------------------------------------------------------------
__device__ __forceinline__ float xla_tanh(float x) {
    const float kClamp = 7.99881172180175781f;
    float xc = fminf(fmaxf(x, -kClamp), kClamp);
    float x2 = xc * xc;
    float p = fmaf(x2, -2.76076847742355e-16f, 2.00018790482477e-13f);
    p = fmaf(x2, p, -8.60467152213735e-11f);
    p = fmaf(x2, p,  5.12229709037114e-08f);
    p = fmaf(x2, p,  1.48572235717979e-05f);
    p = fmaf(x2, p,  6.37261928875436e-04f);
    p = fmaf(x2, p,  4.89352455891786e-03f);
    p = xc * p;
    float q = fmaf(x2, 1.19825839466702e-06f, 1.18534705686654e-04f);
    q = fmaf(x2, q, 2.26843463243900e-03f);
    q = fmaf(x2, q, 4.89352518554385e-03f);
    float r = p / q;
    return (fabsf(x) < 0.0004f) ? x : r;
}

// ---------------------------------------------------------------------------
// K_A: A[k][m] = sum_j qv[k][j] * kv[m][j]
// ---------------------------------------------------------------------------
__global__ void kA(const float* __restrict__ qv, const float* __restrict__ kv) {
    __shared__ float wk[DD];
    int m = blockIdx.x, k = threadIdx.x;
    wk[k] = kv[m * DD + k];
    __syncthreads();
    float s = 0.f;
    #pragma unroll 8
    for (int j = 0; j < DD; j++) s = fmaf(qv[k * DD + j], wk[j], s);
    g_A[k * DD + m] = s;
}

// ---------------------------------------------------------------------------
// K_T: hT[b][d][n] = hvec[b][n][d]
// ---------------------------------------------------------------------------
__global__ void kT(const float* __restrict__ hvec) {
    __shared__ float tile[32][33];
    int b = blockIdx.z;
    int n0 = blockIdx.x * 32, d0 = blockIdx.y * 32;
    int tx = threadIdx.x, ty = threadIdx.y;   // 32 x 8
    #pragma unroll
    for (int i = 0; i < 32; i += 8)
        tile[ty + i][tx] = hvec[((size_t)b * NN + n0 + ty + i) * DD + d0 + tx];
    __syncthreads();
    #pragma unroll
    for (int i = 0; i < 32; i += 8)
        g_hT[((size_t)b * DD + d0 + ty + i) * NN + n0 + tx] = tile[tx][ty + i];
}

// ---------------------------------------------------------------------------
// K_Vec: hbarA[b][m] = sum_k hbar[b][k]*A[k][m]; vA (b==0). Seq-k, coalesced A.
// ---------------------------------------------------------------------------
__global__ void kVec(const float* __restrict__ hbar,
                     const float* __restrict__ vec1,
                     const float* __restrict__ vecf) {
    __shared__ float hb[DD], vv[DD];
    int b = blockIdx.x, m = threadIdx.x;
    hb[m] = hbar[b * DD + m];
    if (b == 0) vv[m] = vec1[m] + vecf[m];
    __syncthreads();
    float acc = 0.f;
    #pragma unroll 8
    for (int k = 0; k < DD; k++) acc = fmaf(hb[k], g_A[k * DD + m], acc);
    g_hbarA[b * DD + m] = acc;
    if (b == 0) {
        float a2 = 0.f;
        #pragma unroll 8
        for (int k = 0; k < DD; k++) a2 = fmaf(vv[k], g_A[k * DD + m], a2);
        g_vA[m] = a2;
    }
}

// ---------------------------------------------------------------------------
// K_Gemm: C[b][r0+i][c0+j] = sum_d A[b][d][r0+i] * B[b][d][c0+j]
// 128x128 tile, 256 threads, 8x8 per thread with split columns
// {tx*4, 64+tx*4} (conflict-free LDS). FFMA2; strictly d-sequential per lane.
// ---------------------------------------------------------------------------
extern __shared__ float dynsm[];
__global__ void __launch_bounds__(256, 2)
kGemm(float* __restrict__ Cg, const float* __restrict__ Ag,
      const float* __restrict__ Bg,
      size_t sAb, size_t sBb, size_t sCb, int ldA, int ldB, int ldC) {
    float* Ms = dynsm;               // [64][GSTR]
    float* Hs = dynsm + 64 * GSTR;   // [64][GSTR]
    int b = blockIdx.z;
    int r0 = blockIdx.y * 128, c0 = blockIdx.x * 128;
    int tid = threadIdx.x;
    int ty = tid >> 4;       // 0..15 -> rows ty*8 .. +8
    int tx = tid & 15;       // cols tx*4 and 64+tx*4

    const float* Ab = Ag + (size_t)b * sAb;
    const float* Bb = Bg + (size_t)b * sBb;

    unsigned long long acc2[32];     // [row r][pair c] = acc2[r*4+c]
    #pragma unroll
    for (int j = 0; j < 32; j++) acc2[j] = 0ull;

    for (int dc = 0; dc < 2; dc++) {
        __syncthreads();
        for (int i = tid; i < 64 * 32; i += 256) {
            int d = i >> 5, v = i & 31;
            ((float4*)(Ms + d * GSTR))[v] =
                ((const float4*)(Ab + (size_t)(dc * 64 + d) * ldA + r0))[v];
            ((float4*)(Hs + d * GSTR))[v] =
                ((const float4*)(Bb + (size_t)(dc * 64 + d) * ldB + c0))[v];
        }
        __syncthreads();
        #pragma unroll 4
        for (int d = 0; d < 64; d++) {
            const float4* ar = (const float4*)(Ms + d * GSTR + ty * 8);
            float4 A0 = ar[0], A1 = ar[1];                    // broadcast in quarter
            ulonglong2 B0 = *(const ulonglong2*)(Hs + d * GSTR + tx * 4);
            ulonglong2 B1 = *(const ulonglong2*)(Hs + d * GSTR + 64 + tx * 4);
            unsigned long long bl[4] = {B0.x, B0.y, B1.x, B1.y};
            float af[8] = {A0.x, A0.y, A0.z, A0.w, A1.x, A1.y, A1.z, A1.w};
            #pragma unroll
            for (int r = 0; r < 8; r++) {
                unsigned long long ad = pack2(af[r], af[r]);
                #pragma unroll
                for (int c = 0; c < 4; c++) ffma2(acc2[r * 4 + c], bl[c], ad);
            }
        }
    }
    #pragma unroll
    for (int r = 0; r < 8; r++) {
        float* crow = Cg + (size_t)b * sCb + (size_t)(r0 + ty * 8 + r) * ldC + c0;
        ulonglong2 w0; w0.x = acc2[r * 4 + 0]; w0.y = acc2[r * 4 + 1];
        ulonglong2 w1; w1.x = acc2[r * 4 + 2]; w1.y = acc2[r * 4 + 3];
        *(ulonglong2*)(crow + tx * 4) = w0;
        *(ulonglong2*)(crow + 64 + tx * 4) = w1;
    }
}

// ---------------------------------------------------------------------------
// K_D: sequential greedy decode (unchanged from R8 - passed).
// ---------------------------------------------------------------------------
__global__ void __launch_bounds__(384) kD(const float* __restrict__ hvec,
                                          float* __restrict__ out) {
    __shared__ float sb[DD], sv[DD];
    __shared__ float rv[32]; __shared__ int ri[32]; __shared__ float rs[32];
    const int b = blockIdx.x, tid = threadIdx.x;
    const int lane = tid & 31, wid = tid >> 5;

    if (tid < DD) { sb[tid] = g_hbarA[b * DD + tid]; sv[tid] = g_vA[tid]; }
    __syncthreads();

    float sHB, sV;
    {
        const float4* h4 = (const float4*)(hvec + ((size_t)b * NN + tid) * DD);
        float a0 = 0.f, a1 = 0.f, a2 = 0.f, a3 = 0.f;
        float c0 = 0.f, c1 = 0.f, c2 = 0.f, c3 = 0.f;
        #pragma unroll
        for (int j = 0; j < 32; j++) {
            float4 h = h4[j];
            a0 = fmaf(h.x, sb[4 * j + 0], a0); c0 = fmaf(h.x, sv[4 * j + 0], c0);
            a1 = fmaf(h.y, sb[4 * j + 1], a1); c1 = fmaf(h.y, sv[4 * j + 1], c1);
            a2 = fmaf(h.z, sb[4 * j + 2], a2); c2 = fmaf(h.z, sv[4 * j + 2], c2);
            a3 = fmaf(h.w, sb[4 * j + 3], a3); c3 = fmaf(h.w, sv[4 * j + 3], c3);
        }
        sHB = (a0 + a1) + (a2 + a3);
        sV  = (c0 + c1) + (c2 + c3);
    }

    const float* Gb = g_G + (size_t)b * NN * NN;
    bool  vis  = false;
    float logp = 0.f, sbf = 0.f;
    int   a    = 0;

    for (int t = 0; t < NN; t++) {
        float s;
        if (t == 0) {
            s = sHB + sV;
        } else {
            float gv = __ldg(Gb + (size_t)a * NN + tid);
            if (t == 1) sbf = sHB + gv;
            s = sbf + gv;
        }

        float score  = 10.f * xla_tanh(s * 0.25f);
        float masked = vis ? NEGV : score;
        float ep     = __expf(masked);

        float v = masked; int idx = tid; float es = ep;
        #pragma unroll
        for (int o = 16; o > 0; o >>= 1) {
            float v2 = __shfl_xor_sync(0xffffffffu, v, o);
            int   i2 = __shfl_xor_sync(0xffffffffu, idx, o);
            float e2 = __shfl_xor_sync(0xffffffffu, es, o);
            es += e2;
            if (v2 > v || (v2 == v && i2 < idx)) { v = v2; idx = i2; }
        }
        const int par = (t & 1) ? 16 : 0;
        if (lane == 0) { rv[par + wid] = v; ri[par + wid] = idx; rs[par + wid] = es; }
        __syncthreads();

        float m  = rv[par];
        int   am = ri[par];
        float ss = rs[par];
        #pragma unroll
        for (int w = 1; w < NWARP; w++) {
            float v2 = rv[par + w];
            int   i2 = ri[par + w];
            ss += rs[par + w];
            if (v2 > m || (v2 == m && i2 < am)) { m = v2; am = i2; }
        }
        a = am;
        if (tid == a) vis = true;
        if (tid == 0) {
            out[t * BB + b] = (float)a;
            logp += m - __logf(ss);
        }
    }
    if (tid == 0) out[NN * BB + b] = logp;
}

// ---------------------------------------------------------------------------
extern "C" void kernel_launch(void* const* d_in, const int* in_sizes, int n_in,
                              void* d_out, int out_size) {
    const float* hvec = (const float*)d_in[0];
    const float* hbar = (const float*)d_in[1];
    const float* qvp  = (const float*)d_in[2];
    const float* kvp  = (const float*)d_in[3];
    const float* vec1 = (const float*)d_in[4];
    const float* vecf = (const float*)d_in[5];
    float* out = (float*)d_out;

    const int smG = 2 * 64 * GSTR * 4;   // 67584 B per CTA
    cudaFuncSetAttribute(kGemm, cudaFuncAttributeMaxDynamicSharedMemorySize, smG);

    float *pA, *pHT, *pMT, *pG;
    cudaGetSymbolAddress((void**)&pA,  g_A);
    cudaGetSymbolAddress((void**)&pHT, g_hT);
    cudaGetSymbolAddress((void**)&pMT, g_MT);
    cudaGetSymbolAddress((void**)&pG,  g_G);

    kA<<<DD, DD>>>(qvp, kvp);
    kT<<<dim3(NN / 32, DD / 32, BB), dim3(32, 8)>>>(hvec);
    kVec<<<BB, DD>>>(hbar, vec1, vecf);
    // MT[b][m][a] = sum_k A[k][m] * hT[b][k][a]   (A batch-stride 0)
    kGemm<<<dim3(NN / 128, 1, BB), 256, smG>>>(
        pMT, pA, pHT, 0, (size_t)DD * NN, (size_t)DD * NN, DD, NN, NN);
    // G[b][a][n] = sum_d MT[b][d][a] * hT[b][d][n]
    kGemm<<<dim3(NN / 128, NN / 128, BB), 256, smG>>>(
        pG, pMT, pHT, (size_t)DD * NN, (size_t)DD * NN, (size_t)NN * NN, NN, NN, NN);
    kD<<<BB, 384>>>(hvec, out);
}

// round 10
// speedup vs baseline: 1.7253x; 1.0506x over previous
#include <cuda_runtime.h>
#include <math.h>

#define BB 256
#define NN 384
#define DD 128
#define NEGV -1e9f
#define NWARP 12
#define GSTR 132
#define CH 32

// ---------------- device scratch (static, no allocation) ----------------
__device__ float g_A[DD * DD];
__device__ float g_hT[BB * DD * NN];
__device__ float g_MT[BB * DD * NN];
__device__ float g_G[(size_t)BB * NN * NN];
__device__ float g_hbarA[BB * DD];
__device__ float g_vA[DD];

// ---------------- packed fp32x2 helpers ----------------
__device__ __forceinline__ void ffma2(unsigned long long& d,
                                      unsigned long long a,
                                      unsigned long long b) {
    asm("fma.rn.f32x2 %0, %1, %2, %0;" : "+l"(d) : "l"(a), "l"(b));
}
__device__ __forceinline__ unsigned long long pack2(float lo, float hi) {
    unsigned long long r;
    asm("mov.b64 %0, {%1, %2};" : "=l"(r) : "f"(lo), "f"(hi));
    return r;
}

// order-preserving float<->u32 (total order == fp32 compare; no NaNs here)
__device__ __forceinline__ unsigned orderf(float f) {
    unsigned b = __float_as_uint(f);
    return (b & 0x80000000u) ? ~b : (b | 0x80000000u);
}
__device__ __forceinline__ float unorderf(unsigned o) {
    unsigned b = (o & 0x80000000u) ? (o & 0x7fffffffu) : ~o;
    return __uint_as_float(b);
}

// ---------------------------------------------------------------------------
// Bit-faithful port of XLA's EmitFastTanh (with_fma=true). DO NOT TOUCH.
// ---------------------------------------------------------------------------
__device__ __forceinline__ float xla_tanh(float x) {
    const float kClamp = 7.99881172180175781f;
    float xc = fminf(fmaxf(x, -kClamp), kClamp);
    float x2 = xc * xc;
    float p = fmaf(x2, -2.76076847742355e-16f, 2.00018790482477e-13f);
    p = fmaf(x2, p, -8.60467152213735e-11f);
    p = fmaf(x2, p,  5.12229709037114e-08f);
    p = fmaf(x2, p,  1.48572235717979e-05f);
    p = fmaf(x2, p,  6.37261928875436e-04f);
    p = fmaf(x2, p,  4.89352455891786e-03f);
    p = xc * p;
    float q = fmaf(x2, 1.19825839466702e-06f, 1.18534705686654e-04f);
    q = fmaf(x2, q, 2.26843463243900e-03f);
    q = fmaf(x2, q, 4.89352518554385e-03f);
    float r = p / q;
    return (fabsf(x) < 0.0004f) ? x : r;
}

// ---------------------------------------------------------------------------
__global__ void kA(const float* __restrict__ qv, const float* __restrict__ kv) {
    __shared__ float wk[DD];
    int m = blockIdx.x, k = threadIdx.x;
    wk[k] = kv[m * DD + k];
    __syncthreads();
    float s = 0.f;
    #pragma unroll 8
    for (int j = 0; j < DD; j++) s = fmaf(qv[k * DD + j], wk[j], s);
    g_A[k * DD + m] = s;
}

__global__ void kT(const float* __restrict__ hvec) {
    __shared__ float tile[32][33];
    int b = blockIdx.z;
    int n0 = blockIdx.x * 32, d0 = blockIdx.y * 32;
    int tx = threadIdx.x, ty = threadIdx.y;
    #pragma unroll
    for (int i = 0; i < 32; i += 8)
        tile[ty + i][tx] = hvec[((size_t)b * NN + n0 + ty + i) * DD + d0 + tx];
    __syncthreads();
    #pragma unroll
    for (int i = 0; i < 32; i += 8)
        g_hT[((size_t)b * DD + d0 + ty + i) * NN + n0 + tx] = tile[tx][ty + i];
}

__global__ void kVec(const float* __restrict__ hbar,
                     const float* __restrict__ vec1,
                     const float* __restrict__ vecf) {
    __shared__ float hb[DD], vv[DD];
    int b = blockIdx.x, m = threadIdx.x;
    hb[m] = hbar[b * DD + m];
    if (b == 0) vv[m] = vec1[m] + vecf[m];
    __syncthreads();
    float acc = 0.f;
    #pragma unroll 8
    for (int k = 0; k < DD; k++) acc = fmaf(hb[k], g_A[k * DD + m], acc);
    g_hbarA[b * DD + m] = acc;
    if (b == 0) {
        float a2 = 0.f;
        #pragma unroll 8
        for (int k = 0; k < DD; k++) a2 = fmaf(vv[k], g_A[k * DD + m], a2);
        g_vA[m] = a2;
    }
}

// ---------------------------------------------------------------------------
// K_Gemm: C[b][r0+i][c0+j] = sum_d A[b][d][r0+i]*B[b][d][c0+j]
// 128x128 tile, 8x8/thread split-column layout, cp.async double buffering
// over 4 chunks of 32 d-rows. d-order strictly ascending -> bit-identical.
// ---------------------------------------------------------------------------
extern __shared__ float dynsm[];
__device__ __forceinline__ void cpa16(unsigned s, const void* g) {
    asm volatile("cp.async.ca.shared.global [%0], [%1], 16;" :: "r"(s), "l"(g));
}

__global__ void __launch_bounds__(256, 2)
kGemm(float* __restrict__ Cg, const float* __restrict__ Ag,
      const float* __restrict__ Bg,
      size_t sAb, size_t sBb, size_t sCb, int ldA, int ldB, int ldC) {
    int b = blockIdx.z;
    int r0 = blockIdx.y * 128, c0 = blockIdx.x * 128;
    int tid = threadIdx.x;
    int ty = tid >> 4, tx = tid & 15;

    const float* Ab = Ag + (size_t)b * sAb;
    const float* Bb = Bg + (size_t)b * sBb;
    unsigned sbase = (unsigned)__cvta_generic_to_shared(dynsm);

    unsigned long long acc2[32];
    #pragma unroll
    for (int j = 0; j < 32; j++) acc2[j] = 0ull;

    // issue chunk c into stage st
    auto issue = [&](int c, int st) {
        unsigned Ms = sbase + (unsigned)(st * 2 * CH * GSTR) * 4u;
        unsigned Hs = Ms + (unsigned)(CH * GSTR) * 4u;
        const float* Asrc = Ab + (size_t)(c * CH) * ldA + r0;
        const float* Bsrc = Bb + (size_t)(c * CH) * ldB + c0;
        #pragma unroll
        for (int i = tid; i < CH * 32; i += 256) {
            int d = i >> 5, v = i & 31;
            cpa16(Ms + (unsigned)(d * GSTR + v * 4) * 4u, Asrc + (size_t)d * ldA + v * 4);
            cpa16(Hs + (unsigned)(d * GSTR + v * 4) * 4u, Bsrc + (size_t)d * ldB + v * 4);
        }
        asm volatile("cp.async.commit_group;");
    };

    issue(0, 0);
    #pragma unroll
    for (int c = 0; c < 4; c++) {
        if (c < 3) {
            issue(c + 1, (c + 1) & 1);
            asm volatile("cp.async.wait_group 1;");
        } else {
            asm volatile("cp.async.wait_group 0;");
        }
        __syncthreads();
        float* Ms = dynsm + (c & 1) * 2 * CH * GSTR;
        float* Hs = Ms + CH * GSTR;
        #pragma unroll 4
        for (int d = 0; d < CH; d++) {
            const float4* ar = (const float4*)(Ms + d * GSTR + ty * 8);
            float4 A0 = ar[0], A1 = ar[1];
            ulonglong2 B0 = *(const ulonglong2*)(Hs + d * GSTR + tx * 4);
            ulonglong2 B1 = *(const ulonglong2*)(Hs + d * GSTR + 64 + tx * 4);
            unsigned long long bl[4] = {B0.x, B0.y, B1.x, B1.y};
            float af[8] = {A0.x, A0.y, A0.z, A0.w, A1.x, A1.y, A1.z, A1.w};
            #pragma unroll
            for (int r = 0; r < 8; r++) {
                unsigned long long ad = pack2(af[r], af[r]);
                #pragma unroll
                for (int cc = 0; cc < 4; cc++) ffma2(acc2[r * 4 + cc], bl[cc], ad);
            }
        }
        __syncthreads();
    }
    #pragma unroll
    for (int r = 0; r < 8; r++) {
        float* crow = Cg + (size_t)b * sCb + (size_t)(r0 + ty * 8 + r) * ldC + c0;
        ulonglong2 w0; w0.x = acc2[r * 4 + 0]; w0.y = acc2[r * 4 + 1];
        ulonglong2 w1; w1.x = acc2[r * 4 + 2]; w1.y = acc2[r * 4 + 3];
        *(ulonglong2*)(crow + tx * 4) = w0;
        *(ulonglong2*)(crow + 64 + tx * 4) = w1;
    }
}

// ---------------------------------------------------------------------------
// K_D: sequential greedy decode. redux-based argmax + speculative L2 prefetch.
// ---------------------------------------------------------------------------
__global__ void __launch_bounds__(384) kD(const float* __restrict__ hvec,
                                          float* __restrict__ out) {
    __shared__ float sb[DD], sv[DD];
    __shared__ unsigned long long rk[32];
    __shared__ float rs[32];
    const int b = blockIdx.x, tid = threadIdx.x;
    const int lane = tid & 31, wid = tid >> 5;

    if (tid < DD) { sb[tid] = g_hbarA[b * DD + tid]; sv[tid] = g_vA[tid]; }
    if (tid < 32) { rk[tid] = 1023ull; rs[tid] = 0.f; }   // valid idx 0 keys
    __syncthreads();

    float sHB, sV;
    {
        const float4* h4 = (const float4*)(hvec + ((size_t)b * NN + tid) * DD);
        float a0 = 0.f, a1 = 0.f, a2 = 0.f, a3 = 0.f;
        float c0 = 0.f, c1 = 0.f, c2 = 0.f, c3 = 0.f;
        #pragma unroll
        for (int j = 0; j < 32; j++) {
            float4 h = h4[j];
            a0 = fmaf(h.x, sb[4 * j + 0], a0); c0 = fmaf(h.x, sv[4 * j + 0], c0);
            a1 = fmaf(h.y, sb[4 * j + 1], a1); c1 = fmaf(h.y, sv[4 * j + 1], c1);
            a2 = fmaf(h.z, sb[4 * j + 2], a2); c2 = fmaf(h.z, sv[4 * j + 2], c2);
            a3 = fmaf(h.w, sb[4 * j + 3], a3); c3 = fmaf(h.w, sv[4 * j + 3], c3);
        }
        sHB = (a0 + a1) + (a2 + a3);
        sV  = (c0 + c1) + (c2 + c3);
    }

    const float* Gb = g_G + (size_t)b * NN * NN;
    bool  vis  = false;
    float logp = 0.f, sbf = 0.f;
    int   a    = 0;

    for (int t = 0; t < NN; t++) {
        float s;
        if (t == 0) {
            s = sHB + sV;
        } else {
            float gv = __ldg(Gb + (size_t)a * NN + tid);
            if (t == 1) sbf = sHB + gv;
            s = sbf + gv;
        }

        float score  = 10.f * xla_tanh(s * 0.25f);
        float masked = vis ? NEGV : score;
        float ep     = __expf(masked);

        // HW warp argmax: max ordered value, lowest lane on ties
        unsigned ov   = orderf(masked);
        unsigned wmax = __reduce_max_sync(0xffffffffu, ov);
        unsigned bal  = __ballot_sync(0xffffffffu, ov == wmax);
        int widx = (wid << 5) + (__ffs(bal) - 1);

        // exp-sum (independent chain, overlaps)
        float es = ep;
        #pragma unroll
        for (int o = 16; o > 0; o >>= 1)
            es += __shfl_xor_sync(0xffffffffu, es, o);

        unsigned long long key =
            ((unsigned long long)wmax << 32) | (unsigned)(1023 - widx);
        const int par = (t & 1) ? 16 : 0;
        if (lane == 0) { rk[par + wid] = key; rs[par + wid] = es; }

        // speculative prefetch of tentative winner's G row (racy peek; safe)
        {
            unsigned long long pk = rk[par];
            #pragma unroll
            for (int w = 1; w < NWARP; w++) {
                unsigned long long k2 = rk[par + w];
                if (k2 > pk) pk = k2;
            }
            int pidx = (1023 - (int)(pk & 1023u)) & 1023;
            if (pidx > NN - 1) pidx = 0;
            if (lane < 12) {
                const char* pp = (const char*)(Gb + (size_t)pidx * NN) + (lane << 7);
                asm volatile("prefetch.global.L2 [%0];" :: "l"(pp));
            }
        }
        __syncthreads();

        // block combine: u64 max (tree), es sum (fixed order)
        unsigned long long bk = rk[par];
        float ss = rs[par];
        #pragma unroll
        for (int w = 1; w < NWARP; w++) {
            unsigned long long k2 = rk[par + w];
            if (k2 > bk) bk = k2;
            ss += rs[par + w];
        }
        a = 1023 - (int)(bk & 1023u);
        if (tid == a) vis = true;
        if (tid == 0) {
            out[t * BB + b] = (float)a;
            float m = unorderf((unsigned)(bk >> 32));
            logp += m - __logf(ss);
        }
    }
    if (tid == 0) out[NN * BB + b] = logp;
}

// ---------------------------------------------------------------------------
extern "C" void kernel_launch(void* const* d_in, const int* in_sizes, int n_in,
                              void* d_out, int out_size) {
    const float* hvec = (const float*)d_in[0];
    const float* hbar = (const float*)d_in[1];
    const float* qvp  = (const float*)d_in[2];
    const float* kvp  = (const float*)d_in[3];
    const float* vec1 = (const float*)d_in[4];
    const float* vecf = (const float*)d_in[5];
    float* out = (float*)d_out;

    const int smG = 4 * CH * GSTR * 4;   // 67584 B (2 stages x 2 mats x 32 x GSTR)
    cudaFuncSetAttribute(kGemm, cudaFuncAttributeMaxDynamicSharedMemorySize, smG);

    float *pA, *pHT, *pMT, *pG;
    cudaGetSymbolAddress((void**)&pA,  g_A);
    cudaGetSymbolAddress((void**)&pHT, g_hT);
    cudaGetSymbolAddress((void**)&pMT, g_MT);
    cudaGetSymbolAddress((void**)&pG,  g_G);

    kA<<<DD, DD>>>(qvp, kvp);
    kT<<<dim3(NN / 32, DD / 32, BB), dim3(32, 8)>>>(hvec);
    kVec<<<BB, DD>>>(hbar, vec1, vecf);
    kGemm<<<dim3(NN / 128, 1, BB), 256, smG>>>(
        pMT, pA, pHT, 0, (size_t)DD * NN, (size_t)DD * NN, DD, NN, NN);
    kGemm<<<dim3(NN / 128, NN / 128, BB), 256, smG>>>(
        pG, pMT, pHT, (size_t)DD * NN, (size_t)DD * NN, (size_t)NN * NN, NN, NN, NN);
    kD<<<BB, 384>>>(hvec, out);
}